// round 8
// baseline (speedup 1.0000x reference)
#include <cuda_runtime.h>
#include <math.h>

#define NN 50000
#define NE 500000
#define HID 256
#define NLAYERS 15
#define EPSV 1e-5f
#define NROWB ((NN + 127) / 128)   // 391 row blocks over nodes

// ---------------- device scratch (no allocations allowed) ----------------
__device__ float g_h  [(size_t)NN * HID];
__device__ float g_agg[(size_t)NN * HID];
__device__ float g_out[(size_t)NN * HID];
__device__ float g_uv [(size_t)2 * NN * HID];   // u = h@W1a.T | v = h@W1b.T
__device__ float g_part[(size_t)2 * NE];        // partial dots from edge GEMM
__device__ int   g_rowptr[NN + 1];
__device__ int   g_woff[NN];
__device__ int   g_hist[NN];
__device__ int   g_colidx[NE];
__device__ float g_psum[NROWB * HID];
__device__ float g_psq [NROWB * HID];
__device__ float g_scale[HID];
__device__ float g_shift[HID];

// ---------------- CSR build (deterministic) ----------------
__global__ void k_zero_hist() {
    int i = blockIdx.x * blockDim.x + threadIdx.x;
    if (i < NN) g_hist[i] = 0;
}

__global__ void k_hist(const int* __restrict__ dst) {
    int e = blockIdx.x * blockDim.x + threadIdx.x;
    if (e < NE) atomicAdd(&g_hist[dst[e]], 1);
}

__global__ void k_scan() {
    __shared__ int ss[1024];
    int t = threadIdx.x;
    int s0 = t * 49;
    int s1 = s0 + 49;
    if (s0 > NN) s0 = NN;
    if (s1 > NN) s1 = NN;
    int s = 0;
    for (int i = s0; i < s1; i++) s += g_hist[i];
    ss[t] = s;
    __syncthreads();
    for (int off = 1; off < 1024; off <<= 1) {
        int v = (t >= off) ? ss[t - off] : 0;
        __syncthreads();
        ss[t] += v;
        __syncthreads();
    }
    int run = (t > 0) ? ss[t - 1] : 0;
    for (int i = s0; i < s1; i++) {
        g_rowptr[i] = run;
        g_woff[i]   = run;
        run += g_hist[i];
    }
    if (t == 1023) g_rowptr[NN] = ss[1023];
}

__global__ void k_scatter(const int* __restrict__ dst) {
    int e = blockIdx.x * blockDim.x + threadIdx.x;
    if (e < NE) {
        int p = atomicAdd(&g_woff[dst[e]], 1);
        g_colidx[p] = e;   // edge id; sorted per bucket below -> deterministic
    }
}

__global__ void k_sortbuckets(const int* __restrict__ src) {
    int n = blockIdx.x * blockDim.x + threadIdx.x;
    if (n >= NN) return;
    int s = g_rowptr[n], t = g_rowptr[n + 1];
    for (int i = s + 1; i < t; i++) {
        int v = g_colidx[i];
        int j = i - 1;
        while (j >= s && g_colidx[j] > v) { g_colidx[j + 1] = g_colidx[j]; j--; }
        g_colidx[j + 1] = v;
    }
    for (int i = s; i < t; i++) g_colidx[i] = src[g_colidx[i]];
}

// ---------------- input FC: h = x @ W_in.T  (IN_CH = 2) ----------------
__global__ void k_infc(const float* __restrict__ x, const float* __restrict__ Win) {
    __shared__ float w0[HID], w1[HID];
    int j = threadIdx.x;
    w0[j] = Win[2 * j];
    w1[j] = Win[2 * j + 1];
    __syncthreads();
    for (int i = blockIdx.x; i < NN; i += gridDim.x) {
        float a = x[2 * i], b = x[2 * i + 1];
        g_h[(size_t)i * HID + j] = a * w0[j] + b * w1[j];
    }
}

// ---------------- SpMM: agg[n] = sum over in-edges of h[src] ----------------
__global__ void k_spmm() {
    int warp = threadIdx.x >> 5, lane = threadIdx.x & 31;
    int n = blockIdx.x * 8 + warp;
    if (n >= NN) return;
    int s = g_rowptr[n], e = g_rowptr[n + 1];
    float4 a0 = make_float4(0.f, 0.f, 0.f, 0.f);
    float4 a1 = make_float4(0.f, 0.f, 0.f, 0.f);
    for (int i = s; i < e; i++) {
        int sr = g_colidx[i];
        const float4* p = (const float4*)(g_h + (size_t)sr * HID);
        float4 v0 = p[lane];
        float4 v1 = p[lane + 32];
        a0.x += v0.x; a0.y += v0.y; a0.z += v0.z; a0.w += v0.w;
        a1.x += v1.x; a1.y += v1.y; a1.z += v1.z; a1.w += v1.w;
    }
    float4* q = (float4*)(g_agg + (size_t)n * HID);
    q[lane]      = a0;
    q[lane + 32] = a1;
}

// ---------------- tf32 helpers ----------------
__device__ __forceinline__ void mma_tf32(float c[4], const unsigned a[4],
                                         unsigned b0, unsigned b1) {
    asm volatile(
        "mma.sync.aligned.m16n8k8.row.col.f32.tf32.tf32.f32 "
        "{%0,%1,%2,%3}, {%4,%5,%6,%7}, {%8,%9}, {%0,%1,%2,%3};"
        : "+f"(c[0]), "+f"(c[1]), "+f"(c[2]), "+f"(c[3])
        : "r"(a[0]), "r"(a[1]), "r"(a[2]), "r"(a[3]), "r"(b0), "r"(b1));
}

// split fp32 -> (hi, lo) tf32 pair; hi + lo captures ~21 mantissa bits
__device__ __forceinline__ void split1(float v, unsigned& h, unsigned& l) {
    asm("cvt.rna.tf32.f32 %0, %1;" : "=r"(h) : "f"(v));
    float lo = v - __uint_as_float(h);
    asm("cvt.rna.tf32.f32 %0, %1;" : "=r"(l) : "f"(lo));
}

// ---------------- tf32x3 MMA GEMM, 128x128x16 tile, 8 warps (32x64 each) ----
// MODE 0: C=g_out, A=[g_agg|g_h] (K=512), B=[B0(Wrel)|B1(Wroot)], +bias,
//         epilogue also emits per-block column sum/sumsq partials (fused stats)
// MODE 1: C=g_uv+VSEL*NN*HID, A=g_h (K=256), B=B0 (W1 pre-offset, ldb=512)
// MODE 2: A[e,k]=relu(u[src]+v[dst]+b1[k]) on the fly (K=256), B=W2 (256x256);
//         epilogue: partial dot relu(acc+b2)·w3 -> g_part[bx*NE+e] (race-free)
template <int MODE, int VSEL>
__global__ void __launch_bounds__(256) k_mma(
    const float* __restrict__ B0, const float* __restrict__ B1,
    const float* __restrict__ bias,   // MODE0: brel; MODE2: b2
    const float* __restrict__ w3,     // MODE2
    const float* __restrict__ b1e,    // MODE2
    const int* __restrict__ esrc, const int* __restrict__ edst)
{
    constexpr int M = (MODE == 2) ? NE : NN;
    constexpr int KTOT = (MODE == 0) ? 512 : 256;
    constexpr int LDS = 20;   // row stride (words): conflict-free frag loads

    __shared__ unsigned As_h[128][LDS], As_l[128][LDS];
    __shared__ unsigned Bs_h[128][LDS], Bs_l[128][LDS];
    __shared__ int s_src[128], s_dst[128];
    __shared__ float sred[4][128], qred[4][128];

    const int tid = threadIdx.x;
    const int m0 = blockIdx.y * 128, n0 = blockIdx.x * 128;

    if (MODE == 2) {
        if (tid < 128) {
            int m = m0 + tid;
            s_src[tid] = (m < M) ? esrc[m] : 0;
        } else {
            int m = m0 + tid - 128;
            s_dst[tid - 128] = (m < M) ? edst[m] : 0;
        }
        __syncthreads();
    }

    const int lane = tid & 31, warp = tid >> 5;
    const int wm0 = (warp & 3) * 32, wn0 = (warp >> 2) * 64;
    const int g = lane >> 2, qc = lane & 3;

    float acc[2][8][4];
#pragma unroll
    for (int mi = 0; mi < 2; mi++)
#pragma unroll
        for (int ni = 0; ni < 8; ni++)
#pragma unroll
            for (int q = 0; q < 4; q++) acc[mi][ni][q] = 0.f;

    const int lr = tid >> 1;        // load row 0..127
    const int lk = (tid & 1) * 8;   // k offset: 0 or 8

    for (int k0 = 0; k0 < KTOT; k0 += 16) {
        // -------- global loads (8 A floats + 8 B floats per thread) --------
        float4 a0 = make_float4(0.f, 0.f, 0.f, 0.f), a1 = a0;
        {
            int m = m0 + lr;
            int ka = k0 + lk;
            if (m < M) {
                if (MODE == 0) {
                    const float* ap = ((ka < 256) ? g_agg : g_h)
                                      + (size_t)m * HID + (ka & 255);
                    a0 = *(const float4*)ap;
                    a1 = *(const float4*)(ap + 4);
                } else if (MODE == 1) {
                    const float* ap = g_h + (size_t)m * HID + ka;
                    a0 = *(const float4*)ap;
                    a1 = *(const float4*)(ap + 4);
                } else {
                    const float* up = g_uv + (size_t)s_src[lr] * HID + ka;
                    const float* vp = g_uv + ((size_t)NN + s_dst[lr]) * HID + ka;
                    float4 u0 = *(const float4*)up, u1 = *(const float4*)(up + 4);
                    float4 v0 = *(const float4*)vp, v1 = *(const float4*)(vp + 4);
                    float4 c0 = *(const float4*)(b1e + ka);
                    float4 c1 = *(const float4*)(b1e + ka + 4);
                    a0.x = fmaxf(u0.x + v0.x + c0.x, 0.f);
                    a0.y = fmaxf(u0.y + v0.y + c0.y, 0.f);
                    a0.z = fmaxf(u0.z + v0.z + c0.z, 0.f);
                    a0.w = fmaxf(u0.w + v0.w + c0.w, 0.f);
                    a1.x = fmaxf(u1.x + v1.x + c1.x, 0.f);
                    a1.y = fmaxf(u1.y + v1.y + c1.y, 0.f);
                    a1.z = fmaxf(u1.z + v1.z + c1.z, 0.f);
                    a1.w = fmaxf(u1.w + v1.w + c1.w, 0.f);
                }
            }
        }
        float4 b0v, b1v;
        {
            int nr = n0 + lr;
            int kb = k0 + lk;
            const float* bp;
            if (MODE == 0)      bp = ((kb < 256) ? B0 : B1) + nr * 256 + (kb & 255);
            else if (MODE == 1) bp = B0 + nr * 512 + kb;
            else                bp = B0 + nr * 256 + kb;
            b0v = *(const float4*)bp;
            b1v = *(const float4*)(bp + 4);
        }

        __syncthreads();   // previous iter's smem reads done

        // -------- split to tf32 hi/lo, store to smem --------
        {
            unsigned h[8], l[8];
            float va[8] = {a0.x, a0.y, a0.z, a0.w, a1.x, a1.y, a1.z, a1.w};
#pragma unroll
            for (int i = 0; i < 8; i++) split1(va[i], h[i], l[i]);
            *(uint4*)&As_h[lr][lk]     = make_uint4(h[0], h[1], h[2], h[3]);
            *(uint4*)&As_h[lr][lk + 4] = make_uint4(h[4], h[5], h[6], h[7]);
            *(uint4*)&As_l[lr][lk]     = make_uint4(l[0], l[1], l[2], l[3]);
            *(uint4*)&As_l[lr][lk + 4] = make_uint4(l[4], l[5], l[6], l[7]);
            float vb[8] = {b0v.x, b0v.y, b0v.z, b0v.w, b1v.x, b1v.y, b1v.z, b1v.w};
#pragma unroll
            for (int i = 0; i < 8; i++) split1(vb[i], h[i], l[i]);
            *(uint4*)&Bs_h[lr][lk]     = make_uint4(h[0], h[1], h[2], h[3]);
            *(uint4*)&Bs_h[lr][lk + 4] = make_uint4(h[4], h[5], h[6], h[7]);
            *(uint4*)&Bs_l[lr][lk]     = make_uint4(l[0], l[1], l[2], l[3]);
            *(uint4*)&Bs_l[lr][lk + 4] = make_uint4(l[4], l[5], l[6], l[7]);
        }
        __syncthreads();

        // -------- MMA: 3 products per fragment pair --------
#pragma unroll
        for (int kk = 0; kk < 16; kk += 8) {
            unsigned ah[2][4], al[2][4];
#pragma unroll
            for (int mi = 0; mi < 2; mi++) {
                int r = wm0 + mi * 16 + g;
                ah[mi][0] = As_h[r][kk + qc];     ah[mi][1] = As_h[r + 8][kk + qc];
                ah[mi][2] = As_h[r][kk + qc + 4]; ah[mi][3] = As_h[r + 8][kk + qc + 4];
                al[mi][0] = As_l[r][kk + qc];     al[mi][1] = As_l[r + 8][kk + qc];
                al[mi][2] = As_l[r][kk + qc + 4]; al[mi][3] = As_l[r + 8][kk + qc + 4];
            }
#pragma unroll
            for (int ni = 0; ni < 8; ni++) {
                int c = wn0 + ni * 8 + g;
                unsigned bh0 = Bs_h[c][kk + qc], bh1 = Bs_h[c][kk + qc + 4];
                unsigned bl0 = Bs_l[c][kk + qc], bl1 = Bs_l[c][kk + qc + 4];
#pragma unroll
                for (int mi = 0; mi < 2; mi++) {
                    mma_tf32(acc[mi][ni], ah[mi], bl0, bl1);  // hi*lo
                    mma_tf32(acc[mi][ni], al[mi], bh0, bh1);  // lo*hi
                    mma_tf32(acc[mi][ni], ah[mi], bh0, bh1);  // hi*hi
                }
            }
        }
    }

    // ---------------- epilogues ----------------
    if (MODE == 2) {
        // per-row partial dot over this block's 128 cols (both n-half warps)
        float sums[2][2] = {{0.f, 0.f}, {0.f, 0.f}};
#pragma unroll
        for (int ni = 0; ni < 8; ni++) {
            int cb = n0 + wn0 + ni * 8 + 2 * qc;
            float ba = bias[cb], bb = bias[cb + 1];
            float wa = w3[cb],  wb = w3[cb + 1];
#pragma unroll
            for (int mi = 0; mi < 2; mi++) {
                sums[mi][0] += fmaxf(acc[mi][ni][0] + ba, 0.f) * wa
                             + fmaxf(acc[mi][ni][1] + bb, 0.f) * wb;
                sums[mi][1] += fmaxf(acc[mi][ni][2] + ba, 0.f) * wa
                             + fmaxf(acc[mi][ni][3] + bb, 0.f) * wb;
            }
        }
        __syncthreads();
#pragma unroll
        for (int mi = 0; mi < 2; mi++)
#pragma unroll
            for (int h = 0; h < 2; h++) {
                float s = sums[mi][h];
                s += __shfl_xor_sync(0xffffffffu, s, 1);
                s += __shfl_xor_sync(0xffffffffu, s, 2);
                if (qc == 0)
                    sred[warp >> 2][wm0 + mi * 16 + h * 8 + g] = s;  // n-half slot
            }
        __syncthreads();
        if (tid < 128) {
            int m = m0 + tid;
            if (m < M)
                g_part[(size_t)blockIdx.x * NE + m] = sred[0][tid] + sred[1][tid];
        }
    } else if (MODE == 0) {
        // store C (+bias) AND per-block column stats partials
#pragma unroll
        for (int ni = 0; ni < 8; ni++) {
            int col = n0 + wn0 + ni * 8 + 2 * qc;
            float bx = bias[col], by = bias[col + 1];
            float sa = 0.f, sb = 0.f, qa = 0.f, qb = 0.f;
#pragma unroll
            for (int mi = 0; mi < 2; mi++) {
                int r0 = m0 + wm0 + mi * 16 + g, r1 = r0 + 8;
                float v0 = acc[mi][ni][0] + bx, v1 = acc[mi][ni][1] + by;
                float v2 = acc[mi][ni][2] + bx, v3 = acc[mi][ni][3] + by;
                if (r0 < M) {
                    *(float2*)(g_out + (size_t)r0 * HID + col) = make_float2(v0, v1);
                    sa += v0; qa += v0 * v0; sb += v1; qb += v1 * v1;
                }
                if (r1 < M) {
                    *(float2*)(g_out + (size_t)r1 * HID + col) = make_float2(v2, v3);
                    sa += v2; qa += v2 * v2; sb += v3; qb += v3 * v3;
                }
            }
#pragma unroll
            for (int off = 4; off <= 16; off <<= 1) {
                sa += __shfl_xor_sync(0xffffffffu, sa, off);
                sb += __shfl_xor_sync(0xffffffffu, sb, off);
                qa += __shfl_xor_sync(0xffffffffu, qa, off);
                qb += __shfl_xor_sync(0xffffffffu, qb, off);
            }
            if (g == 0) {
                int c = wn0 + ni * 8 + 2 * qc;
                sred[warp & 3][c] = sa; sred[warp & 3][c + 1] = sb;
                qred[warp & 3][c] = qa; qred[warp & 3][c + 1] = qb;
            }
        }
        __syncthreads();
        if (tid < 128) {
            float s = sred[0][tid] + sred[1][tid] + sred[2][tid] + sred[3][tid];
            float q = qred[0][tid] + qred[1][tid] + qred[2][tid] + qred[3][tid];
            g_psum[blockIdx.y * HID + n0 + tid] = s;
            g_psq [blockIdx.y * HID + n0 + tid] = q;
        }
    } else {
        float* crow = g_uv + (size_t)VSEL * NN * HID;
#pragma unroll
        for (int mi = 0; mi < 2; mi++)
#pragma unroll
            for (int ni = 0; ni < 8; ni++) {
                int col = n0 + wn0 + ni * 8 + 2 * qc;
                int r0 = m0 + wm0 + mi * 16 + g, r1 = r0 + 8;
                if (r0 < M)
                    *(float2*)(crow + (size_t)r0 * HID + col) =
                        make_float2(acc[mi][ni][0], acc[mi][ni][1]);
                if (r1 < M)
                    *(float2*)(crow + (size_t)r1 * HID + col) =
                        make_float2(acc[mi][ni][2], acc[mi][ni][3]);
            }
    }
}

// ---------------- batchnorm finalize + update ----------------
__global__ void k_finalize(const float* __restrict__ gamma, const float* __restrict__ beta) {
    int col = threadIdx.x;
    float s = 0.f, q = 0.f;
    for (int b = 0; b < NROWB; b++) {
        s += g_psum[b * HID + col];
        q += g_psq [b * HID + col];
    }
    float mean = s / (float)NN;
    float var = q / (float)NN - mean * mean;   // biased var, matches jnp.var
    float sc = gamma[col] * rsqrtf(var + EPSV);
    g_scale[col] = sc;
    g_shift[col] = beta[col] - mean * sc;
}

// h += relu(out * scale + shift)
__global__ void k_update() {
    int i = blockIdx.x * blockDim.x + threadIdx.x;
    if (i >= NN * HID / 4) return;
    int c4 = (i & 63) << 2;
    float4 o = ((const float4*)g_out)[i];
    float4 h = ((float4*)g_h)[i];
    float v;
    v = o.x * g_scale[c4 + 0] + g_shift[c4 + 0]; h.x += fmaxf(v, 0.f);
    v = o.y * g_scale[c4 + 1] + g_shift[c4 + 1]; h.y += fmaxf(v, 0.f);
    v = o.z * g_scale[c4 + 2] + g_shift[c4 + 2]; h.z += fmaxf(v, 0.f);
    v = o.w * g_scale[c4 + 3] + g_shift[c4 + 3]; h.w += fmaxf(v, 0.f);
    ((float4*)g_h)[i] = h;
}

// ---------------- combine partial dots -> sigmoid ----------------
__global__ void k_sig(const float* __restrict__ b3, float* __restrict__ out) {
    int e = blockIdx.x * blockDim.x + threadIdx.x;
    if (e < NE)
        out[e] = 1.f / (1.f + expf(-(g_part[e] + g_part[NE + e] + b3[0])));
}

// ---------------- launch ----------------
extern "C" void kernel_launch(void* const* d_in, const int* in_sizes, int n_in,
                              void* d_out, int out_size) {
    const float* x     = (const float*)d_in[0];
    const int*   ei    = (const int*)  d_in[1];
    const float* Win   = (const float*)d_in[2];
    const float* Wrel  = (const float*)d_in[3];
    const float* brel  = (const float*)d_in[4];
    const float* Wroot = (const float*)d_in[5];
    const float* gamma = (const float*)d_in[6];
    const float* beta  = (const float*)d_in[7];
    const float* W1    = (const float*)d_in[8];
    const float* b1    = (const float*)d_in[9];
    const float* W2    = (const float*)d_in[10];
    const float* b2    = (const float*)d_in[11];
    const float* W3    = (const float*)d_in[12];
    const float* b3    = (const float*)d_in[13];
    float* out = (float*)d_out;
    const int* src = ei;
    const int* dst = ei + NE;

    // CSR build (replayed in-graph; deterministic after per-bucket sort)
    k_zero_hist<<<(NN + 255) / 256, 256>>>();
    k_hist<<<(NE + 255) / 256, 256>>>(dst);
    k_scan<<<1, 1024>>>();
    k_scatter<<<(NE + 255) / 256, 256>>>(dst);
    k_sortbuckets<<<(NN + 255) / 256, 256>>>(src);

    k_infc<<<2048, 256>>>(x, Win);

    for (int l = 0; l < NLAYERS; l++) {
        k_spmm<<<(NN + 7) / 8, 256>>>();
        k_mma<0, 0><<<dim3(2, NROWB), 256>>>(
            Wrel + (size_t)l * HID * HID, Wroot + (size_t)l * HID * HID,
            brel + l * HID, nullptr, nullptr, nullptr, nullptr);
        k_finalize<<<1, 256>>>(gamma + l * HID, beta + l * HID);
        k_update<<<(NN * HID / 4 + 255) / 256, 256>>>();
    }

    // edge MLP, decomposed: u = h@W1a.T, v = h@W1b.T (per-node, 10x fewer FLOPs)
    k_mma<1, 0><<<dim3(2, NROWB), 256>>>(W1,       nullptr, nullptr,
                                         nullptr, nullptr, nullptr, nullptr);
    k_mma<1, 1><<<dim3(2, NROWB), 256>>>(W1 + 256, nullptr, nullptr,
                                         nullptr, nullptr, nullptr, nullptr);
    // fused: z1 = relu(u[src]+v[dst]+b1) built in A-load; z2 = z1@W2.T;
    // epilogue computes race-free partial relu(z2+b2)·w3 per 128-col block
    k_mma<2, 0><<<dim3(2, (NE + 127) / 128), 256>>>(W2, nullptr, b2,
                                                    W3, b1, src, dst);
    k_sig<<<(NE + 255) / 256, 256>>>(b3, out);
}

// round 11
// speedup vs baseline: 2.2924x; 2.2924x over previous
#include <cuda_runtime.h>
#include <math.h>

#define NN 50000
#define NE 500000
#define HID 256
#define NLAYERS 15
#define EPSV 1e-5f
#define NROWB ((NN + 127) / 128)   // 391 row blocks over nodes

// ---------------- device scratch (no allocations allowed) ----------------
__device__ float g_h  [(size_t)NN * HID];
__device__ float g_agg[(size_t)NN * HID];
__device__ float g_out[(size_t)NN * HID];
__device__ float g_uv [(size_t)2 * NN * HID];   // u = h@W1a.T | v = h@W1b.T
__device__ float g_part[(size_t)2 * NE];        // partial dots from edge GEMM
__device__ int   g_rowptr[NN + 1];
__device__ int   g_woff[NN];
__device__ int   g_hist[NN];
__device__ int   g_colidx[NE];
__device__ float g_psum[NROWB * HID];
__device__ float g_psq [NROWB * HID];
__device__ float g_scale[HID];
__device__ float g_shift[HID];

// ---------------- CSR build (deterministic) ----------------
__global__ void k_zero_hist() {
    int i = blockIdx.x * blockDim.x + threadIdx.x;
    if (i < NN) g_hist[i] = 0;
}

__global__ void k_hist(const int* __restrict__ dst) {
    int e = blockIdx.x * blockDim.x + threadIdx.x;
    if (e < NE) atomicAdd(&g_hist[dst[e]], 1);
}

__global__ void k_scan() {
    __shared__ int ss[1024];
    int t = threadIdx.x;
    int s0 = t * 49;
    int s1 = s0 + 49;
    if (s0 > NN) s0 = NN;
    if (s1 > NN) s1 = NN;
    int s = 0;
    for (int i = s0; i < s1; i++) s += g_hist[i];
    ss[t] = s;
    __syncthreads();
    for (int off = 1; off < 1024; off <<= 1) {
        int v = (t >= off) ? ss[t - off] : 0;
        __syncthreads();
        ss[t] += v;
        __syncthreads();
    }
    int run = (t > 0) ? ss[t - 1] : 0;
    for (int i = s0; i < s1; i++) {
        g_rowptr[i] = run;
        g_woff[i]   = run;
        run += g_hist[i];
    }
    if (t == 1023) g_rowptr[NN] = ss[1023];
}

__global__ void k_scatter(const int* __restrict__ dst) {
    int e = blockIdx.x * blockDim.x + threadIdx.x;
    if (e < NE) {
        int p = atomicAdd(&g_woff[dst[e]], 1);
        g_colidx[p] = e;   // edge id; sorted per bucket below -> deterministic
    }
}

__global__ void k_sortbuckets(const int* __restrict__ src) {
    int n = blockIdx.x * blockDim.x + threadIdx.x;
    if (n >= NN) return;
    int s = g_rowptr[n], t = g_rowptr[n + 1];
    for (int i = s + 1; i < t; i++) {
        int v = g_colidx[i];
        int j = i - 1;
        while (j >= s && g_colidx[j] > v) { g_colidx[j + 1] = g_colidx[j]; j--; }
        g_colidx[j + 1] = v;
    }
    for (int i = s; i < t; i++) g_colidx[i] = src[g_colidx[i]];
}

// ---------------- input FC: h = x @ W_in.T  (IN_CH = 2) ----------------
__global__ void k_infc(const float* __restrict__ x, const float* __restrict__ Win) {
    __shared__ float w0[HID], w1[HID];
    int j = threadIdx.x;
    w0[j] = Win[2 * j];
    w1[j] = Win[2 * j + 1];
    __syncthreads();
    for (int i = blockIdx.x; i < NN; i += gridDim.x) {
        float a = x[2 * i], b = x[2 * i + 1];
        g_h[(size_t)i * HID + j] = a * w0[j] + b * w1[j];
    }
}

// ---------------- SpMM: agg[n] = sum over in-edges of h[src] ----------------
__global__ void k_spmm() {
    int warp = threadIdx.x >> 5, lane = threadIdx.x & 31;
    int n = blockIdx.x * 8 + warp;
    if (n >= NN) return;
    int s = g_rowptr[n], e = g_rowptr[n + 1];
    float4 a0 = make_float4(0.f, 0.f, 0.f, 0.f);
    float4 a1 = make_float4(0.f, 0.f, 0.f, 0.f);
    for (int i = s; i < e; i++) {
        int sr = g_colidx[i];
        const float4* p = (const float4*)(g_h + (size_t)sr * HID);
        float4 v0 = p[lane];
        float4 v1 = p[lane + 32];
        a0.x += v0.x; a0.y += v0.y; a0.z += v0.z; a0.w += v0.w;
        a1.x += v1.x; a1.y += v1.y; a1.z += v1.z; a1.w += v1.w;
    }
    float4* q = (float4*)(g_agg + (size_t)n * HID);
    q[lane]      = a0;
    q[lane + 32] = a1;
}

// ---------------- tf32 helpers ----------------
__device__ __forceinline__ unsigned f2tf(float f) {
    unsigned u;
    asm("cvt.rna.tf32.f32 %0, %1;" : "=r"(u) : "f"(f));
    return u;
}

__device__ __forceinline__ void mma_tf32(float c[4], const unsigned a[4],
                                         unsigned b0, unsigned b1) {
    asm volatile(
        "mma.sync.aligned.m16n8k8.row.col.f32.tf32.tf32.f32 "
        "{%0,%1,%2,%3}, {%4,%5,%6,%7}, {%8,%9}, {%0,%1,%2,%3};"
        : "+f"(c[0]), "+f"(c[1]), "+f"(c[2]), "+f"(c[3])
        : "r"(a[0]), "r"(a[1]), "r"(a[2]), "r"(a[3]), "r"(b0), "r"(b1));
}

// ------- single-pass tf32 MMA GEMM, 128x128x16 tile, double-buffered -------
// 8 warps, 32x64 warp tiles. Fragment layout verified correct in round 8.
// MODE 0: C=g_out, A=[g_agg|g_h] (K=512), B=[B0(Wrel)|B1(Wroot)], +bias,
//         epilogue also emits per-block column sum/sumsq partials (fused stats)
// MODE 1: C=g_uv+VSEL*NN*HID, A=g_h (K=256), B=B0 (W1 pre-offset, ldb=512)
// MODE 2: A[e,k]=relu(u[src]+v[dst]+b1[k]) on the fly (K=256), B=W2 (256x256);
//         epilogue: partial dot relu(acc+b2)·w3 -> g_part[bx*NE+e] (race-free)
template <int MODE, int VSEL>
__global__ void __launch_bounds__(256) k_mma(
    const float* __restrict__ B0, const float* __restrict__ B1,
    const float* __restrict__ bias,   // MODE0: brel; MODE2: b2
    const float* __restrict__ w3,     // MODE2
    const float* __restrict__ b1e,    // MODE2
    const int* __restrict__ esrc, const int* __restrict__ edst)
{
    constexpr int M = (MODE == 2) ? NE : NN;
    constexpr int KTOT = (MODE == 0) ? 512 : 256;
    constexpr int LDS = 20;            // row stride (words): conflict-free frags
    constexpr int NCH = KTOT / 16;     // k-chunks

    __shared__ unsigned As[2][128][LDS];
    __shared__ unsigned Bs[2][128][LDS];
    __shared__ int s_src[128], s_dst[128];
    __shared__ float sred[4][128], qred[4][128];

    const int tid = threadIdx.x;
    const int m0 = blockIdx.y * 128, n0 = blockIdx.x * 128;

    if (MODE == 2) {
        if (tid < 128) {
            int m = m0 + tid;
            s_src[tid] = (m < M) ? esrc[m] : 0;
        } else {
            int m = m0 + tid - 128;
            s_dst[tid - 128] = (m < M) ? edst[m] : 0;
        }
        __syncthreads();
    }

    const int lane = tid & 31, warp = tid >> 5;
    const int wm0 = (warp & 3) * 32, wn0 = (warp >> 2) * 64;
    const int g = lane >> 2, qc = lane & 3;

    float acc[2][8][4];
#pragma unroll
    for (int mi = 0; mi < 2; mi++)
#pragma unroll
        for (int ni = 0; ni < 8; ni++)
#pragma unroll
            for (int q = 0; q < 4; q++) acc[mi][ni][q] = 0.f;

    const int lr = tid >> 1;        // load row 0..127
    const int lk = (tid & 1) * 8;   // k offset: 0 or 8

    float va[8], vb[8];

    // global load of one 16-wide k-chunk into registers
    auto gload = [&](int k0) {
        float4 a0 = make_float4(0.f, 0.f, 0.f, 0.f), a1 = a0;
        int m = m0 + lr;
        int ka = k0 + lk;
        if (m < M) {
            if (MODE == 0) {
                const float* ap = ((ka < 256) ? g_agg : g_h)
                                  + (size_t)m * HID + (ka & 255);
                a0 = *(const float4*)ap;
                a1 = *(const float4*)(ap + 4);
            } else if (MODE == 1) {
                const float* ap = g_h + (size_t)m * HID + ka;
                a0 = *(const float4*)ap;
                a1 = *(const float4*)(ap + 4);
            } else {
                const float* up = g_uv + (size_t)s_src[lr] * HID + ka;
                const float* vp = g_uv + ((size_t)NN + s_dst[lr]) * HID + ka;
                float4 u0 = *(const float4*)up, u1 = *(const float4*)(up + 4);
                float4 v0 = *(const float4*)vp, v1 = *(const float4*)(vp + 4);
                float4 c0 = *(const float4*)(b1e + ka);
                float4 c1 = *(const float4*)(b1e + ka + 4);
                a0.x = fmaxf(u0.x + v0.x + c0.x, 0.f);
                a0.y = fmaxf(u0.y + v0.y + c0.y, 0.f);
                a0.z = fmaxf(u0.z + v0.z + c0.z, 0.f);
                a0.w = fmaxf(u0.w + v0.w + c0.w, 0.f);
                a1.x = fmaxf(u1.x + v1.x + c1.x, 0.f);
                a1.y = fmaxf(u1.y + v1.y + c1.y, 0.f);
                a1.z = fmaxf(u1.z + v1.z + c1.z, 0.f);
                a1.w = fmaxf(u1.w + v1.w + c1.w, 0.f);
            }
        }
        va[0] = a0.x; va[1] = a0.y; va[2] = a0.z; va[3] = a0.w;
        va[4] = a1.x; va[5] = a1.y; va[6] = a1.z; va[7] = a1.w;
        int nr = n0 + lr;
        int kb = k0 + lk;
        const float* bp;
        if (MODE == 0)      bp = ((kb < 256) ? B0 : B1) + nr * 256 + (kb & 255);
        else if (MODE == 1) bp = B0 + nr * 512 + kb;
        else                bp = B0 + nr * 256 + kb;
        float4 b0v = *(const float4*)bp;
        float4 b1v = *(const float4*)(bp + 4);
        vb[0] = b0v.x; vb[1] = b0v.y; vb[2] = b0v.z; vb[3] = b0v.w;
        vb[4] = b1v.x; vb[5] = b1v.y; vb[6] = b1v.z; vb[7] = b1v.w;
    };

    // convert + store one chunk to smem buffer
    auto sstore = [&](int buf) {
        unsigned h[8];
#pragma unroll
        for (int i = 0; i < 8; i++) h[i] = f2tf(va[i]);
        *(uint4*)&As[buf][lr][lk]     = make_uint4(h[0], h[1], h[2], h[3]);
        *(uint4*)&As[buf][lr][lk + 4] = make_uint4(h[4], h[5], h[6], h[7]);
#pragma unroll
        for (int i = 0; i < 8; i++) h[i] = f2tf(vb[i]);
        *(uint4*)&Bs[buf][lr][lk]     = make_uint4(h[0], h[1], h[2], h[3]);
        *(uint4*)&Bs[buf][lr][lk + 4] = make_uint4(h[4], h[5], h[6], h[7]);
    };

    // MMA over one 16-wide chunk in buffer `buf`
    auto domma = [&](int buf) {
#pragma unroll
        for (int kk = 0; kk < 16; kk += 8) {
            unsigned ah[2][4];
#pragma unroll
            for (int mi = 0; mi < 2; mi++) {
                int r = wm0 + mi * 16 + g;
                ah[mi][0] = As[buf][r][kk + qc];
                ah[mi][1] = As[buf][r + 8][kk + qc];
                ah[mi][2] = As[buf][r][kk + qc + 4];
                ah[mi][3] = As[buf][r + 8][kk + qc + 4];
            }
#pragma unroll
            for (int ni = 0; ni < 8; ni++) {
                int c = wn0 + ni * 8 + g;
                unsigned bh0 = Bs[buf][c][kk + qc];
                unsigned bh1 = Bs[buf][c][kk + qc + 4];
#pragma unroll
                for (int mi = 0; mi < 2; mi++)
                    mma_tf32(acc[mi][ni], ah[mi], bh0, bh1);
            }
        }
    };

    // ---- double-buffered mainloop: one __syncthreads per chunk ----
    gload(0);
    sstore(0);
    __syncthreads();
#pragma unroll 2
    for (int c = 0; c < NCH; c++) {
        if (c + 1 < NCH) gload((c + 1) * 16);
        domma(c & 1);
        if (c + 1 < NCH) sstore((c + 1) & 1);
        __syncthreads();
    }

    // ---------------- epilogues ----------------
    if (MODE == 2) {
        // per-row partial dot over this block's 128 cols (both n-half warps)
        float sums[2][2] = {{0.f, 0.f}, {0.f, 0.f}};
#pragma unroll
        for (int ni = 0; ni < 8; ni++) {
            int cb = n0 + wn0 + ni * 8 + 2 * qc;
            float ba = bias[cb], bb = bias[cb + 1];
            float wa = w3[cb],  wb = w3[cb + 1];
#pragma unroll
            for (int mi = 0; mi < 2; mi++) {
                sums[mi][0] += fmaxf(acc[mi][ni][0] + ba, 0.f) * wa
                             + fmaxf(acc[mi][ni][1] + bb, 0.f) * wb;
                sums[mi][1] += fmaxf(acc[mi][ni][2] + ba, 0.f) * wa
                             + fmaxf(acc[mi][ni][3] + bb, 0.f) * wb;
            }
        }
#pragma unroll
        for (int mi = 0; mi < 2; mi++)
#pragma unroll
            for (int h = 0; h < 2; h++) {
                float s = sums[mi][h];
                s += __shfl_xor_sync(0xffffffffu, s, 1);
                s += __shfl_xor_sync(0xffffffffu, s, 2);
                if (qc == 0)
                    sred[warp >> 2][wm0 + mi * 16 + h * 8 + g] = s;  // n-half slot
            }
        __syncthreads();
        if (tid < 128) {
            int m = m0 + tid;
            if (m < M)
                g_part[(size_t)blockIdx.x * NE + m] = sred[0][tid] + sred[1][tid];
        }
    } else if (MODE == 0) {
        // store C (+bias) AND per-block column stats partials
#pragma unroll
        for (int ni = 0; ni < 8; ni++) {
            int col = n0 + wn0 + ni * 8 + 2 * qc;
            float bx = bias[col], by = bias[col + 1];
            float sa = 0.f, sb = 0.f, qa = 0.f, qb = 0.f;
#pragma unroll
            for (int mi = 0; mi < 2; mi++) {
                int r0 = m0 + wm0 + mi * 16 + g, r1 = r0 + 8;
                float v0 = acc[mi][ni][0] + bx, v1 = acc[mi][ni][1] + by;
                float v2 = acc[mi][ni][2] + bx, v3 = acc[mi][ni][3] + by;
                if (r0 < M) {
                    *(float2*)(g_out + (size_t)r0 * HID + col) = make_float2(v0, v1);
                    sa += v0; qa += v0 * v0; sb += v1; qb += v1 * v1;
                }
                if (r1 < M) {
                    *(float2*)(g_out + (size_t)r1 * HID + col) = make_float2(v2, v3);
                    sa += v2; qa += v2 * v2; sb += v3; qb += v3 * v3;
                }
            }
#pragma unroll
            for (int off = 4; off <= 16; off <<= 1) {
                sa += __shfl_xor_sync(0xffffffffu, sa, off);
                sb += __shfl_xor_sync(0xffffffffu, sb, off);
                qa += __shfl_xor_sync(0xffffffffu, qa, off);
                qb += __shfl_xor_sync(0xffffffffu, qb, off);
            }
            if (g == 0) {
                int c = wn0 + ni * 8 + 2 * qc;
                sred[warp & 3][c] = sa; sred[warp & 3][c + 1] = sb;
                qred[warp & 3][c] = qa; qred[warp & 3][c + 1] = qb;
            }
        }
        __syncthreads();
        if (tid < 128) {
            float s = sred[0][tid] + sred[1][tid] + sred[2][tid] + sred[3][tid];
            float q = qred[0][tid] + qred[1][tid] + qred[2][tid] + qred[3][tid];
            g_psum[blockIdx.y * HID + n0 + tid] = s;
            g_psq [blockIdx.y * HID + n0 + tid] = q;
        }
    } else {
        float* crow = g_uv + (size_t)VSEL * NN * HID;
#pragma unroll
        for (int mi = 0; mi < 2; mi++)
#pragma unroll
            for (int ni = 0; ni < 8; ni++) {
                int col = n0 + wn0 + ni * 8 + 2 * qc;
                int r0 = m0 + wm0 + mi * 16 + g, r1 = r0 + 8;
                if (r0 < M)
                    *(float2*)(crow + (size_t)r0 * HID + col) =
                        make_float2(acc[mi][ni][0], acc[mi][ni][1]);
                if (r1 < M)
                    *(float2*)(crow + (size_t)r1 * HID + col) =
                        make_float2(acc[mi][ni][2], acc[mi][ni][3]);
            }
    }
}

// ---------------- batchnorm finalize + update ----------------
__global__ void k_finalize(const float* __restrict__ gamma, const float* __restrict__ beta) {
    int col = threadIdx.x;
    float s = 0.f, q = 0.f;
    for (int b = 0; b < NROWB; b++) {
        s += g_psum[b * HID + col];
        q += g_psq [b * HID + col];
    }
    float mean = s / (float)NN;
    float var = q / (float)NN - mean * mean;   // biased var, matches jnp.var
    float sc = gamma[col] * rsqrtf(var + EPSV);
    g_scale[col] = sc;
    g_shift[col] = beta[col] - mean * sc;
}

// h += relu(out * scale + shift)
__global__ void k_update() {
    int i = blockIdx.x * blockDim.x + threadIdx.x;
    if (i >= NN * HID / 4) return;
    int c4 = (i & 63) << 2;
    float4 o = ((const float4*)g_out)[i];
    float4 h = ((float4*)g_h)[i];
    float v;
    v = o.x * g_scale[c4 + 0] + g_shift[c4 + 0]; h.x += fmaxf(v, 0.f);
    v = o.y * g_scale[c4 + 1] + g_shift[c4 + 1]; h.y += fmaxf(v, 0.f);
    v = o.z * g_scale[c4 + 2] + g_shift[c4 + 2]; h.z += fmaxf(v, 0.f);
    v = o.w * g_scale[c4 + 3] + g_shift[c4 + 3]; h.w += fmaxf(v, 0.f);
    ((float4*)g_h)[i] = h;
}

// ---------------- combine partial dots -> sigmoid ----------------
__global__ void k_sig(const float* __restrict__ b3, float* __restrict__ out) {
    int e = blockIdx.x * blockDim.x + threadIdx.x;
    if (e < NE)
        out[e] = 1.f / (1.f + expf(-(g_part[e] + g_part[NE + e] + b3[0])));
}

// ---------------- launch ----------------
extern "C" void kernel_launch(void* const* d_in, const int* in_sizes, int n_in,
                              void* d_out, int out_size) {
    const float* x     = (const float*)d_in[0];
    const int*   ei    = (const int*)  d_in[1];
    const float* Win   = (const float*)d_in[2];
    const float* Wrel  = (const float*)d_in[3];
    const float* brel  = (const float*)d_in[4];
    const float* Wroot = (const float*)d_in[5];
    const float* gamma = (const float*)d_in[6];
    const float* beta  = (const float*)d_in[7];
    const float* W1    = (const float*)d_in[8];
    const float* b1    = (const float*)d_in[9];
    const float* W2    = (const float*)d_in[10];
    const float* b2    = (const float*)d_in[11];
    const float* W3    = (const float*)d_in[12];
    const float* b3    = (const float*)d_in[13];
    float* out = (float*)d_out;
    const int* src = ei;
    const int* dst = ei + NE;

    // CSR build (replayed in-graph; deterministic after per-bucket sort)
    k_zero_hist<<<(NN + 255) / 256, 256>>>();
    k_hist<<<(NE + 255) / 256, 256>>>(dst);
    k_scan<<<1, 1024>>>();
    k_scatter<<<(NE + 255) / 256, 256>>>(dst);
    k_sortbuckets<<<(NN + 255) / 256, 256>>>(src);

    k_infc<<<2048, 256>>>(x, Win);

    for (int l = 0; l < NLAYERS; l++) {
        k_spmm<<<(NN + 7) / 8, 256>>>();
        k_mma<0, 0><<<dim3(2, NROWB), 256>>>(
            Wrel + (size_t)l * HID * HID, Wroot + (size_t)l * HID * HID,
            brel + l * HID, nullptr, nullptr, nullptr, nullptr);
        k_finalize<<<1, 256>>>(gamma + l * HID, beta + l * HID);
        k_update<<<(NN * HID / 4 + 255) / 256, 256>>>();
    }

    // edge MLP, decomposed: u = h@W1a.T, v = h@W1b.T (per-node, 10x fewer FLOPs)
    k_mma<1, 0><<<dim3(2, NROWB), 256>>>(W1,       nullptr, nullptr,
                                         nullptr, nullptr, nullptr, nullptr);
    k_mma<1, 1><<<dim3(2, NROWB), 256>>>(W1 + 256, nullptr, nullptr,
                                         nullptr, nullptr, nullptr, nullptr);
    // fused: z1 = relu(u[src]+v[dst]+b1) built in A-load; z2 = z1@W2.T;
    // epilogue computes race-free partial relu(z2+b2)·w3 per 128-col block
    k_mma<2, 0><<<dim3(2, (NE + 127) / 128), 256>>>(W2, nullptr, b2,
                                                    W3, b1, src, dst);
    k_sig<<<(NE + 255) / 256, 256>>>(b3, out);
}

// round 12
// speedup vs baseline: 2.4537x; 1.0703x over previous
#include <cuda_runtime.h>
#include <math.h>

#define NN 50000
#define NE 500000
#define HID 256
#define NLAYERS 15
#define EPSV 1e-5f
#define NROWB ((NN + 127) / 128)   // 391 row blocks over nodes

// ---------------- device scratch (no allocations allowed) ----------------
__device__ float g_h  [(size_t)NN * HID];
__device__ float g_agg[(size_t)NN * HID];
__device__ float g_out[(size_t)NN * HID];
__device__ float g_uv [(size_t)2 * NN * HID];   // u = h@W1a.T | v = h@W1b.T
__device__ float g_part[(size_t)2 * NE];        // partial dots from edge GEMM
__device__ int   g_rowptr[NN + 1];
__device__ int   g_woff[NN];
__device__ int   g_hist[NN];
__device__ int   g_colidx[NE];
__device__ float g_psum[NROWB * HID];
__device__ float g_psq [NROWB * HID];
__device__ float g_scale[HID];
__device__ float g_shift[HID];

// ---------------- CSR build (deterministic) ----------------
__global__ void k_zero_hist() {
    int i = blockIdx.x * blockDim.x + threadIdx.x;
    if (i < NN) g_hist[i] = 0;
}

__global__ void k_hist(const int* __restrict__ dst) {
    int e = blockIdx.x * blockDim.x + threadIdx.x;
    if (e < NE) atomicAdd(&g_hist[dst[e]], 1);
}

__global__ void k_scan() {
    __shared__ int ss[1024];
    int t = threadIdx.x;
    int s0 = t * 49;
    int s1 = s0 + 49;
    if (s0 > NN) s0 = NN;
    if (s1 > NN) s1 = NN;
    int s = 0;
    for (int i = s0; i < s1; i++) s += g_hist[i];
    ss[t] = s;
    __syncthreads();
    for (int off = 1; off < 1024; off <<= 1) {
        int v = (t >= off) ? ss[t - off] : 0;
        __syncthreads();
        ss[t] += v;
        __syncthreads();
    }
    int run = (t > 0) ? ss[t - 1] : 0;
    for (int i = s0; i < s1; i++) {
        g_rowptr[i] = run;
        g_woff[i]   = run;
        run += g_hist[i];
    }
    if (t == 1023) g_rowptr[NN] = ss[1023];
}

__global__ void k_scatter(const int* __restrict__ dst) {
    int e = blockIdx.x * blockDim.x + threadIdx.x;
    if (e < NE) {
        int p = atomicAdd(&g_woff[dst[e]], 1);
        g_colidx[p] = e;   // edge id; sorted per bucket below -> deterministic
    }
}

__global__ void k_sortbuckets(const int* __restrict__ src) {
    int n = blockIdx.x * blockDim.x + threadIdx.x;
    if (n >= NN) return;
    int s = g_rowptr[n], t = g_rowptr[n + 1];
    for (int i = s + 1; i < t; i++) {
        int v = g_colidx[i];
        int j = i - 1;
        while (j >= s && g_colidx[j] > v) { g_colidx[j + 1] = g_colidx[j]; j--; }
        g_colidx[j + 1] = v;
    }
    for (int i = s; i < t; i++) g_colidx[i] = src[g_colidx[i]];
}

// ---------------- input FC: h = x @ W_in.T  (IN_CH = 2) ----------------
__global__ void k_infc(const float* __restrict__ x, const float* __restrict__ Win) {
    __shared__ float w0[HID], w1[HID];
    int j = threadIdx.x;
    w0[j] = Win[2 * j];
    w1[j] = Win[2 * j + 1];
    __syncthreads();
    for (int i = blockIdx.x; i < NN; i += gridDim.x) {
        float a = x[2 * i], b = x[2 * i + 1];
        g_h[(size_t)i * HID + j] = a * w0[j] + b * w1[j];
    }
}

// ---------------- SpMM: agg[n] = sum over in-edges of h[src] ----------------
__global__ void k_spmm() {
    int warp = threadIdx.x >> 5, lane = threadIdx.x & 31;
    int n = blockIdx.x * 8 + warp;
    if (n >= NN) return;
    int s = g_rowptr[n], e = g_rowptr[n + 1];
    float4 a0 = make_float4(0.f, 0.f, 0.f, 0.f);
    float4 a1 = make_float4(0.f, 0.f, 0.f, 0.f);
    for (int i = s; i < e; i++) {
        int sr = g_colidx[i];
        const float4* p = (const float4*)(g_h + (size_t)sr * HID);
        float4 v0 = p[lane];
        float4 v1 = p[lane + 32];
        a0.x += v0.x; a0.y += v0.y; a0.z += v0.z; a0.w += v0.w;
        a1.x += v1.x; a1.y += v1.y; a1.z += v1.z; a1.w += v1.w;
    }
    float4* q = (float4*)(g_agg + (size_t)n * HID);
    q[lane]      = a0;
    q[lane + 32] = a1;
}

// ---------------- tf32 helpers ----------------
__device__ __forceinline__ unsigned f2tf(float f) {
    unsigned u;
    asm("cvt.rna.tf32.f32 %0, %1;" : "=r"(u) : "f"(f));
    return u;
}

__device__ __forceinline__ void mma_tf32(float c[4], const unsigned a[4],
                                         unsigned b0, unsigned b1) {
    asm volatile(
        "mma.sync.aligned.m16n8k8.row.col.f32.tf32.tf32.f32 "
        "{%0,%1,%2,%3}, {%4,%5,%6,%7}, {%8,%9}, {%0,%1,%2,%3};"
        : "+f"(c[0]), "+f"(c[1]), "+f"(c[2]), "+f"(c[3])
        : "r"(a[0]), "r"(a[1]), "r"(a[2]), "r"(a[3]), "r"(b0), "r"(b1));
}

// ------- single-pass tf32 MMA GEMM, 128x128x16 tile, double-buffered -------
// 8 warps, 32x64 warp tiles. 2 blocks/SM enforced (reg cap 128) for latency
// hiding across the per-chunk __syncthreads.
// MODE 0: C=g_out, A=[g_agg|g_h] (K=512), B=[B0(Wrel)|B1(Wroot)], +bias,
//         epilogue also emits per-block column sum/sumsq partials (fused stats)
// MODE 1: C=g_uv+VSEL*NN*HID, A=g_h (K=256), B=B0 (W1 pre-offset, ldb=512)
// MODE 2: A[e,k]=relu(u[src]+v[dst]+b1[k]) on the fly (K=256), B=W2 (256x256);
//         epilogue: partial dot relu(acc+b2)·w3 -> g_part[bx*NE+e] (race-free)
template <int MODE, int VSEL>
__global__ void __launch_bounds__(256, 2) k_mma(
    const float* __restrict__ B0, const float* __restrict__ B1,
    const float* __restrict__ bias,   // MODE0: brel; MODE2: b2
    const float* __restrict__ w3,     // MODE2
    const float* __restrict__ b1e,    // MODE2
    const int* __restrict__ esrc, const int* __restrict__ edst)
{
    constexpr int M = (MODE == 2) ? NE : NN;
    constexpr int KTOT = (MODE == 0) ? 512 : 256;
    constexpr int LDS = 20;            // row stride (words): conflict-free frags
    constexpr int NCH = KTOT / 16;     // k-chunks

    __shared__ unsigned As[2][128][LDS];
    __shared__ unsigned Bs[2][128][LDS];
    __shared__ int s_src[128], s_dst[128];
    __shared__ float sred[4][128], qred[4][128];

    const int tid = threadIdx.x;
    const int m0 = blockIdx.y * 128, n0 = blockIdx.x * 128;

    if (MODE == 2) {
        if (tid < 128) {
            int m = m0 + tid;
            s_src[tid] = (m < M) ? esrc[m] : 0;
        } else {
            int m = m0 + tid - 128;
            s_dst[tid - 128] = (m < M) ? edst[m] : 0;
        }
        __syncthreads();
    }

    const int lane = tid & 31, warp = tid >> 5;
    const int wm0 = (warp & 3) * 32, wn0 = (warp >> 2) * 64;
    const int g = lane >> 2, qc = lane & 3;

    float acc[2][8][4];
#pragma unroll
    for (int mi = 0; mi < 2; mi++)
#pragma unroll
        for (int ni = 0; ni < 8; ni++)
#pragma unroll
            for (int q = 0; q < 4; q++) acc[mi][ni][q] = 0.f;

    const int lr = tid >> 1;        // load row 0..127
    const int lk = (tid & 1) * 8;   // k offset: 0 or 8

    float va[8], vb[8];

    // global load of one 16-wide k-chunk into registers
    auto gload = [&](int k0) {
        float4 a0 = make_float4(0.f, 0.f, 0.f, 0.f), a1 = a0;
        int m = m0 + lr;
        int ka = k0 + lk;
        if (m < M) {
            if (MODE == 0) {
                const float* ap = ((ka < 256) ? g_agg : g_h)
                                  + (size_t)m * HID + (ka & 255);
                a0 = *(const float4*)ap;
                a1 = *(const float4*)(ap + 4);
            } else if (MODE == 1) {
                const float* ap = g_h + (size_t)m * HID + ka;
                a0 = *(const float4*)ap;
                a1 = *(const float4*)(ap + 4);
            } else {
                const float* up = g_uv + (size_t)s_src[lr] * HID + ka;
                const float* vp = g_uv + ((size_t)NN + s_dst[lr]) * HID + ka;
                float4 u0 = *(const float4*)up, u1 = *(const float4*)(up + 4);
                float4 v0 = *(const float4*)vp, v1 = *(const float4*)(vp + 4);
                float4 c0 = *(const float4*)(b1e + ka);
                float4 c1 = *(const float4*)(b1e + ka + 4);
                a0.x = fmaxf(u0.x + v0.x + c0.x, 0.f);
                a0.y = fmaxf(u0.y + v0.y + c0.y, 0.f);
                a0.z = fmaxf(u0.z + v0.z + c0.z, 0.f);
                a0.w = fmaxf(u0.w + v0.w + c0.w, 0.f);
                a1.x = fmaxf(u1.x + v1.x + c1.x, 0.f);
                a1.y = fmaxf(u1.y + v1.y + c1.y, 0.f);
                a1.z = fmaxf(u1.z + v1.z + c1.z, 0.f);
                a1.w = fmaxf(u1.w + v1.w + c1.w, 0.f);
            }
        }
        va[0] = a0.x; va[1] = a0.y; va[2] = a0.z; va[3] = a0.w;
        va[4] = a1.x; va[5] = a1.y; va[6] = a1.z; va[7] = a1.w;
        int nr = n0 + lr;
        int kb = k0 + lk;
        const float* bp;
        if (MODE == 0)      bp = ((kb < 256) ? B0 : B1) + nr * 256 + (kb & 255);
        else if (MODE == 1) bp = B0 + nr * 512 + kb;
        else                bp = B0 + nr * 256 + kb;
        float4 b0v = *(const float4*)bp;
        float4 b1v = *(const float4*)(bp + 4);
        vb[0] = b0v.x; vb[1] = b0v.y; vb[2] = b0v.z; vb[3] = b0v.w;
        vb[4] = b1v.x; vb[5] = b1v.y; vb[6] = b1v.z; vb[7] = b1v.w;
    };

    // convert + store one chunk to smem buffer
    auto sstore = [&](int buf) {
        unsigned h[8];
#pragma unroll
        for (int i = 0; i < 8; i++) h[i] = f2tf(va[i]);
        *(uint4*)&As[buf][lr][lk]     = make_uint4(h[0], h[1], h[2], h[3]);
        *(uint4*)&As[buf][lr][lk + 4] = make_uint4(h[4], h[5], h[6], h[7]);
#pragma unroll
        for (int i = 0; i < 8; i++) h[i] = f2tf(vb[i]);
        *(uint4*)&Bs[buf][lr][lk]     = make_uint4(h[0], h[1], h[2], h[3]);
        *(uint4*)&Bs[buf][lr][lk + 4] = make_uint4(h[4], h[5], h[6], h[7]);
    };

    // MMA over one 16-wide chunk in buffer `buf`
    auto domma = [&](int buf) {
#pragma unroll
        for (int kk = 0; kk < 16; kk += 8) {
            unsigned ah[2][4];
#pragma unroll
            for (int mi = 0; mi < 2; mi++) {
                int r = wm0 + mi * 16 + g;
                ah[mi][0] = As[buf][r][kk + qc];
                ah[mi][1] = As[buf][r + 8][kk + qc];
                ah[mi][2] = As[buf][r][kk + qc + 4];
                ah[mi][3] = As[buf][r + 8][kk + qc + 4];
            }
#pragma unroll
            for (int ni = 0; ni < 8; ni++) {
                int c = wn0 + ni * 8 + g;
                unsigned bh0 = Bs[buf][c][kk + qc];
                unsigned bh1 = Bs[buf][c][kk + qc + 4];
#pragma unroll
                for (int mi = 0; mi < 2; mi++)
                    mma_tf32(acc[mi][ni], ah[mi], bh0, bh1);
            }
        }
    };

    // ---- double-buffered mainloop: one __syncthreads per chunk ----
    gload(0);
    sstore(0);
    __syncthreads();
#pragma unroll 2
    for (int c = 0; c < NCH; c++) {
        if (c + 1 < NCH) gload((c + 1) * 16);
        domma(c & 1);
        if (c + 1 < NCH) sstore((c + 1) & 1);
        __syncthreads();
    }

    // ---------------- epilogues ----------------
    if (MODE == 2) {
        // per-row partial dot over this block's 128 cols (both n-half warps)
        float sums[2][2] = {{0.f, 0.f}, {0.f, 0.f}};
#pragma unroll
        for (int ni = 0; ni < 8; ni++) {
            int cb = n0 + wn0 + ni * 8 + 2 * qc;
            float ba = bias[cb], bb = bias[cb + 1];
            float wa = w3[cb],  wb = w3[cb + 1];
#pragma unroll
            for (int mi = 0; mi < 2; mi++) {
                sums[mi][0] += fmaxf(acc[mi][ni][0] + ba, 0.f) * wa
                             + fmaxf(acc[mi][ni][1] + bb, 0.f) * wb;
                sums[mi][1] += fmaxf(acc[mi][ni][2] + ba, 0.f) * wa
                             + fmaxf(acc[mi][ni][3] + bb, 0.f) * wb;
            }
        }
#pragma unroll
        for (int mi = 0; mi < 2; mi++)
#pragma unroll
            for (int h = 0; h < 2; h++) {
                float s = sums[mi][h];
                s += __shfl_xor_sync(0xffffffffu, s, 1);
                s += __shfl_xor_sync(0xffffffffu, s, 2);
                if (qc == 0)
                    sred[warp >> 2][wm0 + mi * 16 + h * 8 + g] = s;  // n-half slot
            }
        __syncthreads();
        if (tid < 128) {
            int m = m0 + tid;
            if (m < M)
                g_part[(size_t)blockIdx.x * NE + m] = sred[0][tid] + sred[1][tid];
        }
    } else if (MODE == 0) {
        // store C (+bias) AND per-block column stats partials
#pragma unroll
        for (int ni = 0; ni < 8; ni++) {
            int col = n0 + wn0 + ni * 8 + 2 * qc;
            float bx = bias[col], by = bias[col + 1];
            float sa = 0.f, sb = 0.f, qa = 0.f, qb = 0.f;
#pragma unroll
            for (int mi = 0; mi < 2; mi++) {
                int r0 = m0 + wm0 + mi * 16 + g, r1 = r0 + 8;
                float v0 = acc[mi][ni][0] + bx, v1 = acc[mi][ni][1] + by;
                float v2 = acc[mi][ni][2] + bx, v3 = acc[mi][ni][3] + by;
                if (r0 < M) {
                    *(float2*)(g_out + (size_t)r0 * HID + col) = make_float2(v0, v1);
                    sa += v0; qa += v0 * v0; sb += v1; qb += v1 * v1;
                }
                if (r1 < M) {
                    *(float2*)(g_out + (size_t)r1 * HID + col) = make_float2(v2, v3);
                    sa += v2; qa += v2 * v2; sb += v3; qb += v3 * v3;
                }
            }
#pragma unroll
            for (int off = 4; off <= 16; off <<= 1) {
                sa += __shfl_xor_sync(0xffffffffu, sa, off);
                sb += __shfl_xor_sync(0xffffffffu, sb, off);
                qa += __shfl_xor_sync(0xffffffffu, qa, off);
                qb += __shfl_xor_sync(0xffffffffu, qb, off);
            }
            if (g == 0) {
                int c = wn0 + ni * 8 + 2 * qc;
                sred[warp & 3][c] = sa; sred[warp & 3][c + 1] = sb;
                qred[warp & 3][c] = qa; qred[warp & 3][c + 1] = qb;
            }
        }
        __syncthreads();
        if (tid < 128) {
            float s = sred[0][tid] + sred[1][tid] + sred[2][tid] + sred[3][tid];
            float q = qred[0][tid] + qred[1][tid] + qred[2][tid] + qred[3][tid];
            g_psum[blockIdx.y * HID + n0 + tid] = s;
            g_psq [blockIdx.y * HID + n0 + tid] = q;
        }
    } else {
        float* crow = g_uv + (size_t)VSEL * NN * HID;
#pragma unroll
        for (int mi = 0; mi < 2; mi++)
#pragma unroll
            for (int ni = 0; ni < 8; ni++) {
                int col = n0 + wn0 + ni * 8 + 2 * qc;
                int r0 = m0 + wm0 + mi * 16 + g, r1 = r0 + 8;
                if (r0 < M)
                    *(float2*)(crow + (size_t)r0 * HID + col) =
                        make_float2(acc[mi][ni][0], acc[mi][ni][1]);
                if (r1 < M)
                    *(float2*)(crow + (size_t)r1 * HID + col) =
                        make_float2(acc[mi][ni][2], acc[mi][ni][3]);
            }
    }
}

// ---------------- batchnorm finalize (parallel, deterministic) --------------
// one block per column, 128 threads reduce the 391 per-rowblock partials
__global__ void k_finalize(const float* __restrict__ gamma, const float* __restrict__ beta) {
    int col = blockIdx.x;
    int t = threadIdx.x;
    float s = 0.f, q = 0.f;
    for (int b = t; b < NROWB; b += 128) {
        s += g_psum[b * HID + col];
        q += g_psq [b * HID + col];
    }
#pragma unroll
    for (int off = 16; off > 0; off >>= 1) {
        s += __shfl_xor_sync(0xffffffffu, s, off);
        q += __shfl_xor_sync(0xffffffffu, q, off);
    }
    __shared__ float ss[4], qq[4];
    if ((t & 31) == 0) { ss[t >> 5] = s; qq[t >> 5] = q; }
    __syncthreads();
    if (t == 0) {
        s = ss[0] + ss[1] + ss[2] + ss[3];
        q = qq[0] + qq[1] + qq[2] + qq[3];
        float mean = s / (float)NN;
        float var = q / (float)NN - mean * mean;   // biased var, matches jnp.var
        float sc = gamma[col] * rsqrtf(var + EPSV);
        g_scale[col] = sc;
        g_shift[col] = beta[col] - mean * sc;
    }
}

// h += relu(out * scale + shift)
__global__ void k_update() {
    int i = blockIdx.x * blockDim.x + threadIdx.x;
    if (i >= NN * HID / 4) return;
    int c4 = (i & 63) << 2;
    float4 o = ((const float4*)g_out)[i];
    float4 h = ((float4*)g_h)[i];
    float v;
    v = o.x * g_scale[c4 + 0] + g_shift[c4 + 0]; h.x += fmaxf(v, 0.f);
    v = o.y * g_scale[c4 + 1] + g_shift[c4 + 1]; h.y += fmaxf(v, 0.f);
    v = o.z * g_scale[c4 + 2] + g_shift[c4 + 2]; h.z += fmaxf(v, 0.f);
    v = o.w * g_scale[c4 + 3] + g_shift[c4 + 3]; h.w += fmaxf(v, 0.f);
    ((float4*)g_h)[i] = h;
}

// ---------------- combine partial dots -> sigmoid ----------------
__global__ void k_sig(const float* __restrict__ b3, float* __restrict__ out) {
    int e = blockIdx.x * blockDim.x + threadIdx.x;
    if (e < NE)
        out[e] = 1.f / (1.f + expf(-(g_part[e] + g_part[NE + e] + b3[0])));
}

// ---------------- launch ----------------
extern "C" void kernel_launch(void* const* d_in, const int* in_sizes, int n_in,
                              void* d_out, int out_size) {
    const float* x     = (const float*)d_in[0];
    const int*   ei    = (const int*)  d_in[1];
    const float* Win   = (const float*)d_in[2];
    const float* Wrel  = (const float*)d_in[3];
    const float* brel  = (const float*)d_in[4];
    const float* Wroot = (const float*)d_in[5];
    const float* gamma = (const float*)d_in[6];
    const float* beta  = (const float*)d_in[7];
    const float* W1    = (const float*)d_in[8];
    const float* b1    = (const float*)d_in[9];
    const float* W2    = (const float*)d_in[10];
    const float* b2    = (const float*)d_in[11];
    const float* W3    = (const float*)d_in[12];
    const float* b3    = (const float*)d_in[13];
    float* out = (float*)d_out;
    const int* src = ei;
    const int* dst = ei + NE;

    // CSR build (replayed in-graph; deterministic after per-bucket sort)
    k_zero_hist<<<(NN + 255) / 256, 256>>>();
    k_hist<<<(NE + 255) / 256, 256>>>(dst);
    k_scan<<<1, 1024>>>();
    k_scatter<<<(NE + 255) / 256, 256>>>(dst);
    k_sortbuckets<<<(NN + 255) / 256, 256>>>(src);

    k_infc<<<2048, 256>>>(x, Win);

    for (int l = 0; l < NLAYERS; l++) {
        k_spmm<<<(NN + 7) / 8, 256>>>();
        k_mma<0, 0><<<dim3(2, NROWB), 256>>>(
            Wrel + (size_t)l * HID * HID, Wroot + (size_t)l * HID * HID,
            brel + l * HID, nullptr, nullptr, nullptr, nullptr);
        k_finalize<<<HID, 128>>>(gamma + l * HID, beta + l * HID);
        k_update<<<(NN * HID / 4 + 255) / 256, 256>>>();
    }

    // edge MLP, decomposed: u = h@W1a.T, v = h@W1b.T (per-node, 10x fewer FLOPs)
    k_mma<1, 0><<<dim3(2, NROWB), 256>>>(W1,       nullptr, nullptr,
                                         nullptr, nullptr, nullptr, nullptr);
    k_mma<1, 1><<<dim3(2, NROWB), 256>>>(W1 + 256, nullptr, nullptr,
                                         nullptr, nullptr, nullptr, nullptr);
    // fused: z1 = relu(u[src]+v[dst]+b1) built in A-load; z2 = z1@W2.T;
    // epilogue computes race-free partial relu(z2+b2)·w3 per 128-col block
    k_mma<2, 0><<<dim3(2, (NE + 127) / 128), 256>>>(W2, nullptr, b2,
                                                    W3, b1, src, dst);
    k_sig<<<(NE + 255) / 256, 256>>>(b3, out);
}